// round 1
// baseline (speedup 1.0000x reference)
#include <cuda_runtime.h>

// Folded DCT matrix: M1[k][n] = 0.5 * alpha[k] * cos((2n+1) k pi / 16)
// alpha[0] = 1/sqrt(2), alpha[k>0] = 1.
// Used for all 4 passes (forward uses M1[freq][spatial], inverse uses M1[spatial][freq]).
__constant__ float cM[64] = {
  0.35355339059327378f,  0.35355339059327378f,  0.35355339059327378f,  0.35355339059327378f,
  0.35355339059327378f,  0.35355339059327378f,  0.35355339059327378f,  0.35355339059327378f,

  0.49039264020161522f,  0.41573480615127262f,  0.27778511650980114f,  0.09754516100806412f,
 -0.09754516100806412f, -0.27778511650980114f, -0.41573480615127262f, -0.49039264020161522f,

  0.46193976625564337f,  0.19134171618254492f, -0.19134171618254492f, -0.46193976625564337f,
 -0.46193976625564337f, -0.19134171618254492f,  0.19134171618254492f,  0.46193976625564337f,

  0.41573480615127262f, -0.09754516100806412f, -0.49039264020161522f, -0.27778511650980114f,
  0.27778511650980114f,  0.49039264020161522f,  0.09754516100806412f, -0.41573480615127262f,

  0.35355339059327378f, -0.35355339059327378f, -0.35355339059327378f,  0.35355339059327378f,
  0.35355339059327378f, -0.35355339059327378f, -0.35355339059327378f,  0.35355339059327378f,

  0.27778511650980114f, -0.49039264020161522f,  0.09754516100806412f,  0.41573480615127262f,
 -0.41573480615127262f, -0.09754516100806412f,  0.49039264020161522f, -0.27778511650980114f,

  0.19134171618254492f, -0.46193976625564337f,  0.46193976625564337f, -0.19134171618254492f,
 -0.19134171618254492f,  0.46193976625564337f, -0.46193976625564337f,  0.19134171618254492f,

  0.09754516100806412f, -0.27778511650980114f,  0.41573480615127262f, -0.49039264020161522f,
  0.49039264020161522f, -0.41573480615127262f,  0.27778511650980114f, -0.09754516100806412f
};

// B=32, C=3, H=512, W=512 -> tiles: 32*3*64*64 = 393216
#define N_TILES   393216
#define W_IMG     512
#define TPB       256

__global__ __launch_bounds__(TPB)
void dct_quant_kernel(const float* __restrict__ in,
                      const float* __restrict__ y_table,
                      const float* __restrict__ c_table,
                      const void*  __restrict__ factor_p,
                      float* __restrict__ out)
{
    __shared__ float sQ[3][64];
    __shared__ float sQi[3][64];

    int tid = threadIdx.x;
    if (tid < 192) {
        // factor may arrive as int32 or float32 scalar; disambiguate by bit pattern.
        int   iv = *(const int*)factor_p;
        float f  = (iv >= 1 && iv <= (1 << 20)) ? (float)iv : *(const float*)factor_p;
        int ch = tid >> 6;
        int j  = tid & 63;
        float q = (ch == 0) ? (y_table[j] * f) : (c_table[j] * (0.5f * f));
        sQ[ch][j]  = q;
        sQi[ch][j] = 1.0f / q;
    }
    __syncthreads();

    int tile = blockIdx.x * TPB + tid;
    if (tile >= N_TILES) return;

    int tw = tile & 63;
    int th = (tile >> 6) & 63;
    int bc = tile >> 12;          // b*3 + c, 0..95
    int ch = bc - (bc / 3) * 3;   // channel

    const float* src = in + ((size_t)bc * W_IMG + (size_t)th * 8) * W_IMG + (size_t)tw * 8;

    float X[64];

    // Load + center: (input+1)*127.5 - 127.5 == input*127.5
    #pragma unroll
    for (int r = 0; r < 8; r++) {
        float4 a = *(const float4*)(src + (size_t)r * W_IMG);
        float4 b = *(const float4*)(src + (size_t)r * W_IMG + 4);
        X[r*8+0] = a.x * 127.5f;  X[r*8+1] = a.y * 127.5f;
        X[r*8+2] = a.z * 127.5f;  X[r*8+3] = a.w * 127.5f;
        X[r*8+4] = b.x * 127.5f;  X[r*8+5] = b.y * 127.5f;
        X[r*8+6] = b.z * 127.5f;  X[r*8+7] = b.w * 127.5f;
    }

    // ---- Forward DCT, pass 1: transform each row along y (out index v) ----
    #pragma unroll
    for (int r = 0; r < 8; r++) {
        float t[8];
        #pragma unroll
        for (int y = 0; y < 8; y++) t[y] = X[r*8+y];
        #pragma unroll
        for (int v = 0; v < 8; v++) {
            float s = cM[v*8+0] * t[0];
            #pragma unroll
            for (int y = 1; y < 8; y++) s = fmaf(cM[v*8+y], t[y], s);
            X[r*8+v] = s;
        }
    }
    // ---- Forward DCT, pass 2: transform each column along x (out index u) ----
    #pragma unroll
    for (int col = 0; col < 8; col++) {
        float t[8];
        #pragma unroll
        for (int x = 0; x < 8; x++) t[x] = X[x*8+col];
        #pragma unroll
        for (int u = 0; u < 8; u++) {
            float s = cM[u*8+0] * t[0];
            #pragma unroll
            for (int x = 1; x < 8; x++) s = fmaf(cM[u*8+x], t[x], s);
            X[u*8+col] = s;
        }
    }

    // ---- Quantize / dequantize (diff_round: r + (x-r)^3, round-half-even) ----
    {
        const float* qv = sQ[ch];
        const float* qi = sQi[ch];
        #pragma unroll
        for (int i = 0; i < 64; i++) {
            float q  = X[i] * qi[i];
            float rr = rintf(q);
            float e  = q - rr;
            float dr = fmaf(e * e, e, rr);
            X[i] = dr * qv[i];
        }
    }

    // ---- Inverse DCT, pass 3: columns (sum over x, coeff M1[x][u]) ----
    #pragma unroll
    for (int col = 0; col < 8; col++) {
        float t[8];
        #pragma unroll
        for (int x = 0; x < 8; x++) t[x] = X[x*8+col];
        #pragma unroll
        for (int u = 0; u < 8; u++) {
            float s = cM[0*8+u] * t[0];
            #pragma unroll
            for (int x = 1; x < 8; x++) s = fmaf(cM[x*8+u], t[x], s);
            X[u*8+col] = s;
        }
    }
    // ---- Inverse DCT, pass 4: rows (sum over y, coeff M1[y][v]) ----
    #pragma unroll
    for (int r = 0; r < 8; r++) {
        float t[8];
        #pragma unroll
        for (int y = 0; y < 8; y++) t[y] = X[r*8+y];
        #pragma unroll
        for (int v = 0; v < 8; v++) {
            float s = cM[0*8+v] * t[0];
            #pragma unroll
            for (int y = 1; y < 8; y++) s = fmaf(cM[y*8+v], t[y], s);
            X[r*8+v] = s;
        }
    }

    // ---- Final: +127.5, clip [0,255], /127.5 - 1; store ----
    float* dst = out + ((size_t)bc * W_IMG + (size_t)th * 8) * W_IMG + (size_t)tw * 8;
    const float inv1275 = 1.0f / 127.5f;
    #pragma unroll
    for (int r = 0; r < 8; r++) {
        float o[8];
        #pragma unroll
        for (int v = 0; v < 8; v++) {
            float t = X[r*8+v] + 127.5f;
            t = fminf(fmaxf(t, 0.0f), 255.0f);
            o[v] = fmaf(t, inv1275, -1.0f);
        }
        float4 a = make_float4(o[0], o[1], o[2], o[3]);
        float4 b = make_float4(o[4], o[5], o[6], o[7]);
        *(float4*)(dst + (size_t)r * W_IMG)     = a;
        *(float4*)(dst + (size_t)r * W_IMG + 4) = b;
    }
}

extern "C" void kernel_launch(void* const* d_in, const int* in_sizes, int n_in,
                              void* d_out, int out_size)
{
    // metadata order: input, dct_tensor, dct_scale, idct_tensor, idct_alpha,
    //                 y_table, c_table, factor
    const float* in = (const float*)d_in[0];
    const float* yt = (const float*)d_in[5];
    const float* ct = (const float*)d_in[6];
    const void*  fp = d_in[7];
    float* out = (float*)d_out;

    dim3 grid((N_TILES + TPB - 1) / TPB);
    dct_quant_kernel<<<grid, TPB>>>(in, yt, ct, fp, out);
}

// round 2
// speedup vs baseline: 1.2589x; 1.2589x over previous
#include <cuda_runtime.h>

// B=32, C=3, H=512, W=512 -> tiles: 32*3*64*64 = 393216
#define N_TILES   393216
#define W_IMG     512
#define TPB       128

// Butterfly 8-point DCT-II with folded alpha/0.5 scaling.
// F[k] = sum_n 0.5*alpha_k*cos((2n+1)k pi/16) * t[n]
__device__ __forceinline__ void dct8(float* t) {
    const float c1 = 0.4903926402016152f;
    const float c2 = 0.4619397662556434f;
    const float c3 = 0.4157348061512726f;
    const float c4 = 0.3535533905932738f;
    const float c5 = 0.2777851165098011f;
    const float c6 = 0.1913417161825449f;
    const float c7 = 0.0975451610080641f;

    float s0 = t[0] + t[7], s1 = t[1] + t[6], s2 = t[2] + t[5], s3 = t[3] + t[4];
    float d0 = t[0] - t[7], d1 = t[1] - t[6], d2 = t[2] - t[5], d3 = t[3] - t[4];
    float e0 = s0 + s3, e1 = s1 + s2;
    float f0 = s0 - s3, f1 = s1 - s2;

    t[0] = c4 * (e0 + e1);
    t[4] = c4 * (e0 - e1);
    t[2] = fmaf(c6, f1, c2 * f0);
    t[6] = fmaf(-c2, f1, c6 * f0);
    t[1] = fmaf( c7, d3, fmaf( c5, d2, fmaf( c3, d1, c1 * d0)));
    t[3] = fmaf(-c5, d3, fmaf(-c1, d2, fmaf(-c7, d1, c3 * d0)));
    t[5] = fmaf( c3, d3, fmaf( c7, d2, fmaf(-c1, d1, c5 * d0)));
    t[7] = fmaf(-c1, d3, fmaf( c3, d2, fmaf(-c5, d1, c7 * d0)));
}

// Inverse: out[n] = sum_k 0.5*alpha_k*cos((2n+1)k pi/16) * X[k]
// (transpose of dct8's matrix; includes the 0.25 * idct_alpha folding
//  because 0.25*alpha_u*alpha_v*cos*cos == product of two 0.5*alpha*cos terms)
__device__ __forceinline__ void idct8(float* t) {
    const float c1 = 0.4903926402016152f;
    const float c2 = 0.4619397662556434f;
    const float c3 = 0.4157348061512726f;
    const float c4 = 0.3535533905932738f;
    const float c5 = 0.2777851165098011f;
    const float c6 = 0.1913417161825449f;
    const float c7 = 0.0975451610080641f;

    float a0 = c4 * (t[0] + t[4]);
    float a1 = c4 * (t[0] - t[4]);
    float b0 = fmaf( c6, t[6], c2 * t[2]);
    float b1 = fmaf(-c2, t[6], c6 * t[2]);
    float E0 = a0 + b0, E1 = a1 + b1, E2 = a1 - b1, E3 = a0 - b0;

    float O0 = fmaf( c7, t[7], fmaf( c5, t[5], fmaf( c3, t[3], c1 * t[1])));
    float O1 = fmaf(-c5, t[7], fmaf(-c1, t[5], fmaf(-c7, t[3], c3 * t[1])));
    float O2 = fmaf( c3, t[7], fmaf( c7, t[5], fmaf(-c1, t[3], c5 * t[1])));
    float O3 = fmaf(-c1, t[7], fmaf( c3, t[5], fmaf(-c5, t[3], c7 * t[1])));

    t[0] = E0 + O0;  t[7] = E0 - O0;
    t[1] = E1 + O1;  t[6] = E1 - O1;
    t[2] = E2 + O2;  t[5] = E2 - O2;
    t[3] = E3 + O3;  t[4] = E3 - O3;
}

__global__ __launch_bounds__(TPB)
void dct_quant_kernel(const float* __restrict__ in,
                      const float* __restrict__ y_table,
                      const float* __restrict__ c_table,
                      const void*  __restrict__ factor_p,
                      float* __restrict__ out)
{
    __shared__ float sQ[3][64];
    __shared__ float sQi[3][64];

    int tid = threadIdx.x;
    {
        // factor may arrive as int32 or float32 scalar; disambiguate by bit pattern.
        int   iv = *(const int*)factor_p;
        float f  = (iv >= 1 && iv <= (1 << 20)) ? (float)iv : *(const float*)factor_p;
        // 192 table entries, 128 threads: two strided rounds
        for (int k = tid; k < 192; k += TPB) {
            int ch = k >> 6;
            int j  = k & 63;
            float q = (ch == 0) ? (y_table[j] * f) : (c_table[j] * (0.5f * f));
            sQ[ch][j]  = q;
            sQi[ch][j] = 1.0f / q;
        }
    }
    __syncthreads();

    int tile = blockIdx.x * TPB + tid;

    int tw = tile & 63;
    int th = (tile >> 6) & 63;
    int bc = tile >> 12;          // b*3 + c, 0..95
    int ch = bc - (bc / 3) * 3;   // channel

    const float* src = in + ((size_t)bc * W_IMG + (size_t)th * 8) * W_IMG + (size_t)tw * 8;

    float X[64];

    // Load + center: (input+1)*127.5 - 127.5 == input*127.5
    #pragma unroll
    for (int r = 0; r < 8; r++) {
        float4 a = *(const float4*)(src + (size_t)r * W_IMG);
        float4 b = *(const float4*)(src + (size_t)r * W_IMG + 4);
        X[r*8+0] = a.x * 127.5f;  X[r*8+1] = a.y * 127.5f;
        X[r*8+2] = a.z * 127.5f;  X[r*8+3] = a.w * 127.5f;
        X[r*8+4] = b.x * 127.5f;  X[r*8+5] = b.y * 127.5f;
        X[r*8+6] = b.z * 127.5f;  X[r*8+7] = b.w * 127.5f;
    }

    // Forward DCT: rows then columns
    #pragma unroll
    for (int r = 0; r < 8; r++) {
        dct8(&X[r*8]);
    }
    #pragma unroll
    for (int col = 0; col < 8; col++) {
        float t[8];
        #pragma unroll
        for (int x = 0; x < 8; x++) t[x] = X[x*8+col];
        dct8(t);
        #pragma unroll
        for (int u = 0; u < 8; u++) X[u*8+col] = t[u];
    }

    // Quantize / dequantize (diff_round: r + (x-r)^3, round-half-even)
    {
        const float* qv = sQ[ch];
        const float* qi = sQi[ch];
        #pragma unroll
        for (int i = 0; i < 64; i++) {
            float q  = X[i] * qi[i];
            float rr = rintf(q);
            float e  = q - rr;
            float dr = fmaf(e * e, e, rr);
            X[i] = dr * qv[i];
        }
    }

    // Inverse DCT: columns then rows
    #pragma unroll
    for (int col = 0; col < 8; col++) {
        float t[8];
        #pragma unroll
        for (int x = 0; x < 8; x++) t[x] = X[x*8+col];
        idct8(t);
        #pragma unroll
        for (int u = 0; u < 8; u++) X[u*8+col] = t[u];
    }
    #pragma unroll
    for (int r = 0; r < 8; r++) {
        idct8(&X[r*8]);
    }

    // Final: +127.5, clip [0,255], /127.5 - 1; store
    float* dst = out + ((size_t)bc * W_IMG + (size_t)th * 8) * W_IMG + (size_t)tw * 8;
    const float inv1275 = 1.0f / 127.5f;
    #pragma unroll
    for (int r = 0; r < 8; r++) {
        float o[8];
        #pragma unroll
        for (int v = 0; v < 8; v++) {
            float t = X[r*8+v] + 127.5f;
            t = fminf(fmaxf(t, 0.0f), 255.0f);
            o[v] = fmaf(t, inv1275, -1.0f);
        }
        *(float4*)(dst + (size_t)r * W_IMG)     = make_float4(o[0], o[1], o[2], o[3]);
        *(float4*)(dst + (size_t)r * W_IMG + 4) = make_float4(o[4], o[5], o[6], o[7]);
    }
}

extern "C" void kernel_launch(void* const* d_in, const int* in_sizes, int n_in,
                              void* d_out, int out_size)
{
    // metadata order: input, dct_tensor, dct_scale, idct_tensor, idct_alpha,
    //                 y_table, c_table, factor
    const float* in = (const float*)d_in[0];
    const float* yt = (const float*)d_in[5];
    const float* ct = (const float*)d_in[6];
    const void*  fp = d_in[7];
    float* out = (float*)d_out;

    dim3 grid(N_TILES / TPB);
    dct_quant_kernel<<<grid, TPB>>>(in, yt, ct, fp, out);
}

// round 3
// speedup vs baseline: 1.3128x; 1.0428x over previous
#include <cuda_runtime.h>

// B=32, C=3, H=512, W=512 -> tiles: 32*3*64*64 = 393216
#define N_TILES   393216
#define W_IMG     512
#define TPB       256
// 4 threads per tile (2 rows each). warp = 8 tiles, block = 64 tiles.
#define TILES_PER_BLOCK  (TPB / 4)

// Butterfly 8-point DCT-II with folded alpha/0.5 scaling.
// out[k] = sum_n 0.5*alpha_k*cos((2n+1)k pi/16) * t[n]
__device__ __forceinline__ void dct8(float* t) {
    const float c1 = 0.4903926402016152f;
    const float c2 = 0.4619397662556434f;
    const float c3 = 0.4157348061512726f;
    const float c4 = 0.3535533905932738f;
    const float c5 = 0.2777851165098011f;
    const float c6 = 0.1913417161825449f;
    const float c7 = 0.0975451610080641f;

    float s0 = t[0] + t[7], s1 = t[1] + t[6], s2 = t[2] + t[5], s3 = t[3] + t[4];
    float d0 = t[0] - t[7], d1 = t[1] - t[6], d2 = t[2] - t[5], d3 = t[3] - t[4];
    float e0 = s0 + s3, e1 = s1 + s2;
    float f0 = s0 - s3, f1 = s1 - s2;

    t[0] = c4 * (e0 + e1);
    t[4] = c4 * (e0 - e1);
    t[2] = fmaf(c6, f1, c2 * f0);
    t[6] = fmaf(-c2, f1, c6 * f0);
    t[1] = fmaf( c7, d3, fmaf( c5, d2, fmaf( c3, d1, c1 * d0)));
    t[3] = fmaf(-c5, d3, fmaf(-c1, d2, fmaf(-c7, d1, c3 * d0)));
    t[5] = fmaf( c3, d3, fmaf( c7, d2, fmaf(-c1, d1, c5 * d0)));
    t[7] = fmaf(-c1, d3, fmaf( c3, d2, fmaf(-c5, d1, c7 * d0)));
}

// Inverse (transpose matrix; 0.25*idct_alpha folded): out[n] = sum_k M[k][n]*t[k]
__device__ __forceinline__ void idct8(float* t) {
    const float c1 = 0.4903926402016152f;
    const float c2 = 0.4619397662556434f;
    const float c3 = 0.4157348061512726f;
    const float c4 = 0.3535533905932738f;
    const float c5 = 0.2777851165098011f;
    const float c6 = 0.1913417161825449f;
    const float c7 = 0.0975451610080641f;

    float a0 = c4 * (t[0] + t[4]);
    float a1 = c4 * (t[0] - t[4]);
    float b0 = fmaf( c6, t[6], c2 * t[2]);
    float b1 = fmaf(-c2, t[6], c6 * t[2]);
    float E0 = a0 + b0, E1 = a1 + b1, E2 = a1 - b1, E3 = a0 - b0;

    float O0 = fmaf( c7, t[7], fmaf( c5, t[5], fmaf( c3, t[3], c1 * t[1])));
    float O1 = fmaf(-c5, t[7], fmaf(-c1, t[5], fmaf(-c7, t[3], c3 * t[1])));
    float O2 = fmaf( c3, t[7], fmaf( c7, t[5], fmaf(-c1, t[3], c5 * t[1])));
    float O3 = fmaf(-c1, t[7], fmaf( c3, t[5], fmaf(-c5, t[3], c7 * t[1])));

    t[0] = E0 + O0;  t[7] = E0 - O0;
    t[1] = E1 + O1;  t[6] = E1 - O1;
    t[2] = E2 + O2;  t[5] = E2 - O2;
    t[3] = E3 + O3;  t[4] = E3 - O3;
}

// One butterfly exchange: pair (lo,hi); lane's coord bit = flag.
#define XSTEP(LO, HI, FLAG, MASK) do {                                 \
    float _s = (FLAG) ? (LO) : (HI);                                   \
    float _r = __shfl_xor_sync(0xffffffffu, _s, (MASK));               \
    if (FLAG) (LO) = _r; else (HI) = _r;                               \
} while (0)

// 8x8 transpose. Storage: R[lr][c], lane coord = 2*rr + lr where
// rr = (lane>>3)&3. Row-coord bit0 = lr (local), bit1 = lane bit3, bit2 = lane bit4.
__device__ __forceinline__ void xpose(float R[2][8], int lane) {
    bool f2 = (lane >> 4) & 1;   // row bit2 <-> col bit2, partner mask 16
    #pragma unroll
    for (int lr = 0; lr < 2; lr++) {
        XSTEP(R[lr][0], R[lr][4], f2, 16);
        XSTEP(R[lr][1], R[lr][5], f2, 16);
        XSTEP(R[lr][2], R[lr][6], f2, 16);
        XSTEP(R[lr][3], R[lr][7], f2, 16);
    }
    bool f1 = (lane >> 3) & 1;   // row bit1 <-> col bit1, partner mask 8
    #pragma unroll
    for (int lr = 0; lr < 2; lr++) {
        XSTEP(R[lr][0], R[lr][2], f1, 8);
        XSTEP(R[lr][1], R[lr][3], f1, 8);
        XSTEP(R[lr][4], R[lr][6], f1, 8);
        XSTEP(R[lr][5], R[lr][7], f1, 8);
    }
    // row bit0 (lr) <-> col bit0: local 2x2 block transpose (register perm)
    #pragma unroll
    for (int c = 0; c < 8; c += 2) {
        float tmp = R[0][c+1];
        R[0][c+1] = R[1][c];
        R[1][c]   = tmp;
    }
}

__global__ __launch_bounds__(TPB)
void dct_quant_kernel(const float* __restrict__ in,
                      const float* __restrict__ y_table,
                      const float* __restrict__ c_table,
                      const void*  __restrict__ factor_p,
                      float* __restrict__ out)
{
    // Interleaved (q, 1/q) pairs, per channel, flat index u*8+v.
    __shared__ float2 sQ[3][64];

    int tid = threadIdx.x;
    {
        int   iv = *(const int*)factor_p;
        float f  = (iv >= 1 && iv <= (1 << 20)) ? (float)iv : *(const float*)factor_p;
        if (tid < 192) {
            int ch = tid >> 6;
            int j  = tid & 63;
            float q = (ch == 0) ? (y_table[j] * f) : (c_table[j] * (0.5f * f));
            sQ[ch][j] = make_float2(q, 1.0f / q);
        }
    }
    __syncthreads();

    int lane = tid & 31;
    int t  = lane & 7;          // tile within warp
    int rr = (lane >> 3) & 3;   // row-pair index: rows 2rr, 2rr+1

    int tile = (blockIdx.x * (TPB >> 5) + (tid >> 5)) * 8 + t;
    int tw = tile & 63;
    int th = (tile >> 6) & 63;
    int bc = tile >> 12;
    int ch = bc - (bc / 3) * 3;

    const float* src = in + ((size_t)bc * W_IMG + (size_t)th * 8 + 2 * rr) * W_IMG + (size_t)tw * 8;

    float R[2][8];

    // Load 2 rows + center: (input+1)*127.5 - 127.5 == input*127.5
    #pragma unroll
    for (int lr = 0; lr < 2; lr++) {
        float4 a = *(const float4*)(src + (size_t)lr * W_IMG);
        float4 b = *(const float4*)(src + (size_t)lr * W_IMG + 4);
        R[lr][0] = a.x * 127.5f;  R[lr][1] = a.y * 127.5f;
        R[lr][2] = a.z * 127.5f;  R[lr][3] = a.w * 127.5f;
        R[lr][4] = b.x * 127.5f;  R[lr][5] = b.y * 127.5f;
        R[lr][6] = b.z * 127.5f;  R[lr][7] = b.w * 127.5f;
    }

    // Forward: row DCT (over y), transpose, row DCT (over x)
    dct8(R[0]);  dct8(R[1]);
    xpose(R, lane);                 // now lane coord = v, regs = x
    dct8(R[0]);  dct8(R[1]);        // regs = u; element F[u][v], v = 2rr+lr

    // Quantize / dequantize (diff_round: r + (x-r)^3). q index = u*8 + v.
    {
        const float4* qp = (const float4*)&sQ[ch][0];   // pairs (v, v+1) per 16B
        #pragma unroll
        for (int c = 0; c < 8; c++) {
            float4 qq = qp[c * 4 + rr];  // entries (c*8+2rr): q0,qi0,q1,qi1
            float q0 = R[0][c] * qq.y;
            float r0 = rintf(q0);
            float e0 = q0 - r0;
            R[0][c] = fmaf(e0 * e0, e0, r0) * qq.x;
            float q1 = R[1][c] * qq.w;
            float r1 = rintf(q1);
            float e1 = q1 - r1;
            R[1][c] = fmaf(e1 * e1, e1, r1) * qq.z;
        }
    }

    // Inverse: IDCT over u (regs), transpose, IDCT over v
    idct8(R[0]);  idct8(R[1]);      // regs = x spatial
    xpose(R, lane);                 // lane coord = x, regs = v
    idct8(R[0]);  idct8(R[1]);      // regs = y spatial

    // Final: +127.5, clip [0,255], /127.5 - 1; store
    float* dst = out + ((size_t)bc * W_IMG + (size_t)th * 8 + 2 * rr) * W_IMG + (size_t)tw * 8;
    const float inv1275 = 1.0f / 127.5f;
    #pragma unroll
    for (int lr = 0; lr < 2; lr++) {
        float o[8];
        #pragma unroll
        for (int v = 0; v < 8; v++) {
            float x = R[lr][v] + 127.5f;
            x = fminf(fmaxf(x, 0.0f), 255.0f);
            o[v] = fmaf(x, inv1275, -1.0f);
        }
        *(float4*)(dst + (size_t)lr * W_IMG)     = make_float4(o[0], o[1], o[2], o[3]);
        *(float4*)(dst + (size_t)lr * W_IMG + 4) = make_float4(o[4], o[5], o[6], o[7]);
    }
}

extern "C" void kernel_launch(void* const* d_in, const int* in_sizes, int n_in,
                              void* d_out, int out_size)
{
    // metadata order: input, dct_tensor, dct_scale, idct_tensor, idct_alpha,
    //                 y_table, c_table, factor
    const float* in = (const float*)d_in[0];
    const float* yt = (const float*)d_in[5];
    const float* ct = (const float*)d_in[6];
    const void*  fp = d_in[7];
    float* outp = (float*)d_out;

    dim3 grid(N_TILES / TILES_PER_BLOCK);
    dct_quant_kernel<<<grid, TPB>>>(in, yt, ct, fp, outp);
}

// round 4
// speedup vs baseline: 1.4602x; 1.1123x over previous
#include <cuda_runtime.h>

// B=32, C=3, H=512, W=512 -> tiles: 32*3*64*64 = 393216
#define N_TILES   393216
#define W_IMG     512
#define TPB       256
#define TILES_PER_BLOCK  (TPB / 4)   // 4 threads per tile (packed row-pair each)

typedef unsigned long long ull;

__device__ __forceinline__ ull pk2(float lo, float hi) {
    ull r; asm("mov.b64 %0,{%1,%2};" : "=l"(r) : "f"(lo), "f"(hi)); return r;
}
__device__ __forceinline__ void upk2(ull p, float& lo, float& hi) {
    asm("mov.b64 {%0,%1},%2;" : "=f"(lo), "=f"(hi) : "l"(p));
}
__device__ __forceinline__ ull fadd2(ull a, ull b) {
    ull r; asm("add.rn.f32x2 %0,%1,%2;" : "=l"(r) : "l"(a), "l"(b)); return r;
}
__device__ __forceinline__ ull fmul2(ull a, ull b) {
    ull r; asm("mul.rn.f32x2 %0,%1,%2;" : "=l"(r) : "l"(a), "l"(b)); return r;
}
__device__ __forceinline__ ull ffma2(ull a, ull b, ull c) {
    ull r; asm("fma.rn.f32x2 %0,%1,%2,%3;" : "=l"(r) : "l"(a), "l"(b), "l"(c)); return r;
}

// Packed constants (row-pair identical), incl. negatives and -1 for subtraction.
struct K {
    ull C1, C2, C3, C4, C5, C6, C7;
    ull N1, N2, N5, N7;
    ull NEG1;
};
// a - b  ==  fma(b, -1, a)
#define FSUB2(a, b) ffma2((b), k.NEG1, (a))

// Packed 8-point DCT-II (folded 0.5*alpha scaling), butterfly form.
__device__ __forceinline__ void dct8p(ull* t, const K& k) {
    ull s0 = fadd2(t[0], t[7]), s1 = fadd2(t[1], t[6]);
    ull s2 = fadd2(t[2], t[5]), s3 = fadd2(t[3], t[4]);
    ull d0 = FSUB2(t[0], t[7]), d1 = FSUB2(t[1], t[6]);
    ull d2 = FSUB2(t[2], t[5]), d3 = FSUB2(t[3], t[4]);
    ull e0 = fadd2(s0, s3), e1 = fadd2(s1, s2);
    ull f0 = FSUB2(s0, s3), f1 = FSUB2(s1, s2);

    t[0] = fmul2(k.C4, fadd2(e0, e1));
    t[4] = fmul2(k.C4, FSUB2(e0, e1));
    t[2] = ffma2(k.C6, f1, fmul2(k.C2, f0));
    t[6] = ffma2(k.N2, f1, fmul2(k.C6, f0));
    t[1] = ffma2(k.C7, d3, ffma2(k.C5, d2, ffma2(k.C3, d1, fmul2(k.C1, d0))));
    t[3] = ffma2(k.N5, d3, ffma2(k.N1, d2, ffma2(k.N7, d1, fmul2(k.C3, d0))));
    t[5] = ffma2(k.C3, d3, ffma2(k.C7, d2, ffma2(k.N1, d1, fmul2(k.C5, d0))));
    t[7] = ffma2(k.N1, d3, ffma2(k.C3, d2, ffma2(k.N5, d1, fmul2(k.C7, d0))));
}

// Packed inverse (transpose matrix; 0.25*idct_alpha folded).
__device__ __forceinline__ void idct8p(ull* t, const K& k) {
    ull a0 = fmul2(k.C4, fadd2(t[0], t[4]));
    ull a1 = fmul2(k.C4, FSUB2(t[0], t[4]));
    ull b0 = ffma2(k.C6, t[6], fmul2(k.C2, t[2]));
    ull b1 = ffma2(k.N2, t[6], fmul2(k.C6, t[2]));
    ull E0 = fadd2(a0, b0), E1 = fadd2(a1, b1);
    ull E2 = FSUB2(a1, b1), E3 = FSUB2(a0, b0);

    ull O0 = ffma2(k.C7, t[7], ffma2(k.C5, t[5], ffma2(k.C3, t[3], fmul2(k.C1, t[1]))));
    ull O1 = ffma2(k.N5, t[7], ffma2(k.N1, t[5], ffma2(k.N7, t[3], fmul2(k.C3, t[1]))));
    ull O2 = ffma2(k.C3, t[7], ffma2(k.C7, t[5], ffma2(k.N1, t[3], fmul2(k.C5, t[1]))));
    ull O3 = ffma2(k.N1, t[7], ffma2(k.C3, t[5], ffma2(k.N5, t[3], fmul2(k.C7, t[1]))));

    t[0] = fadd2(E0, O0);  t[7] = FSUB2(E0, O0);
    t[1] = fadd2(E1, O1);  t[6] = FSUB2(E1, O1);
    t[2] = fadd2(E2, O2);  t[5] = FSUB2(E2, O2);
    t[3] = fadd2(E3, O3);  t[4] = FSUB2(E3, O3);
}

// Packed butterfly exchange between P[i] and P[j] across lanes (mask).
#define XSTEPP(I, J, FLAG, MASK) do {                                  \
    ull _s = (FLAG) ? P[I] : P[J];                                     \
    ull _r = __shfl_xor_sync(0xffffffffu, _s, (MASK));                 \
    if (FLAG) P[I] = _r; else P[J] = _r;                               \
} while (0)

// 8x8 transpose on packed row-pairs. Row coord: bit0 = pack-half,
// bit1 = lane bit3, bit2 = lane bit4. Column coord = register index.
__device__ __forceinline__ void xposep(ull P[8], int lane) {
    bool f2 = (lane >> 4) & 1;
    XSTEPP(0, 4, f2, 16);  XSTEPP(1, 5, f2, 16);
    XSTEPP(2, 6, f2, 16);  XSTEPP(3, 7, f2, 16);
    bool f1 = (lane >> 3) & 1;
    XSTEPP(0, 2, f1, 8);   XSTEPP(1, 3, f1, 8);
    XSTEPP(4, 6, f1, 8);   XSTEPP(5, 7, f1, 8);
    // bit0 (pack-half) <-> column bit0: repack halves, register-rename cheap.
    #pragma unroll
    for (int c = 0; c < 8; c += 2) {
        float a0, a1, b0, b1;
        upk2(P[c], a0, a1);
        upk2(P[c + 1], b0, b1);
        P[c]     = pk2(a0, b0);
        P[c + 1] = pk2(a1, b1);
    }
}

__global__ __launch_bounds__(TPB)
void dct_quant_kernel(const float* __restrict__ in,
                      const float* __restrict__ y_table,
                      const float* __restrict__ c_table,
                      const void*  __restrict__ factor_p,
                      float* __restrict__ out)
{
    // Interleaved (q, 1/q) pairs, per channel, flat index u*8+v.
    __shared__ float2 sQ[3][64];

    int tid = threadIdx.x;
    {
        int   iv = *(const int*)factor_p;
        float f  = (iv >= 1 && iv <= (1 << 20)) ? (float)iv : *(const float*)factor_p;
        if (tid < 192) {
            int ch = tid >> 6;
            int j  = tid & 63;
            float q = (ch == 0) ? (y_table[j] * f) : (c_table[j] * (0.5f * f));
            sQ[ch][j] = make_float2(q, 1.0f / q);
        }
    }
    __syncthreads();

    K k;
    k.C1 = pk2( 0.4903926402016152f,  0.4903926402016152f);
    k.C2 = pk2( 0.4619397662556434f,  0.4619397662556434f);
    k.C3 = pk2( 0.4157348061512726f,  0.4157348061512726f);
    k.C4 = pk2( 0.3535533905932738f,  0.3535533905932738f);
    k.C5 = pk2( 0.2777851165098011f,  0.2777851165098011f);
    k.C6 = pk2( 0.1913417161825449f,  0.1913417161825449f);
    k.C7 = pk2( 0.0975451610080641f,  0.0975451610080641f);
    k.N1 = pk2(-0.4903926402016152f, -0.4903926402016152f);
    k.N2 = pk2(-0.4619397662556434f, -0.4619397662556434f);
    k.N5 = pk2(-0.2777851165098011f, -0.2777851165098011f);
    k.N7 = pk2(-0.0975451610080641f, -0.0975451610080641f);
    k.NEG1 = pk2(-1.0f, -1.0f);
    ull C127 = pk2(127.5f, 127.5f);

    int lane = tid & 31;
    int t  = lane & 7;          // tile within warp
    int rr = (lane >> 3) & 3;   // row-pair index: rows 2rr, 2rr+1

    int tile = (blockIdx.x * (TPB >> 5) + (tid >> 5)) * 8 + t;
    int tw = tile & 63;
    int th = (tile >> 6) & 63;
    int bc = tile >> 12;
    int ch = bc - (bc / 3) * 3;

    const float* src = in + ((size_t)bc * W_IMG + (size_t)th * 8 + 2 * rr) * W_IMG + (size_t)tw * 8;

    ull P[8];

    // Load 2 rows, pack pairs, center: (input+1)*127.5 - 127.5 == input*127.5
    {
        float4 a0 = *(const float4*)(src);
        float4 b0 = *(const float4*)(src + 4);
        float4 a1 = *(const float4*)(src + W_IMG);
        float4 b1 = *(const float4*)(src + W_IMG + 4);
        P[0] = fmul2(pk2(a0.x, a1.x), C127);
        P[1] = fmul2(pk2(a0.y, a1.y), C127);
        P[2] = fmul2(pk2(a0.z, a1.z), C127);
        P[3] = fmul2(pk2(a0.w, a1.w), C127);
        P[4] = fmul2(pk2(b0.x, b1.x), C127);
        P[5] = fmul2(pk2(b0.y, b1.y), C127);
        P[6] = fmul2(pk2(b0.z, b1.z), C127);
        P[7] = fmul2(pk2(b0.w, b1.w), C127);
    }

    // Forward: DCT over y (regs), transpose, DCT over x (regs)
    dct8p(P, k);
    xposep(P, lane);            // lane/pack coord = v, regs = x
    dct8p(P, k);                // regs = u; element F[u][v], v = 2rr + half

    // Quantize / dequantize (diff_round: r + (x-r)^3). q index = u*8 + v.
    {
        const float4* qp = (const float4*)&sQ[ch][0];   // (q0,qi0,q1,qi1) per 16B
        #pragma unroll
        for (int c = 0; c < 8; c++) {
            float4 qq = qp[c * 4 + rr];
            ull QI = pk2(qq.y, qq.w);
            ull QV = pk2(qq.x, qq.z);
            ull q  = fmul2(P[c], QI);
            float q0, q1; upk2(q, q0, q1);
            ull rp = pk2(rintf(q0), rintf(q1));
            ull e  = FSUB2(q, rp);
            ull dr = ffma2(fmul2(e, e), e, rp);
            P[c] = fmul2(dr, QV);
        }
    }

    // Inverse: IDCT over u (regs), transpose, IDCT over v (regs)
    idct8p(P, k);               // regs = x spatial
    xposep(P, lane);            // lane/pack coord = x, regs = v
    idct8p(P, k);               // regs/pack = y spatial rows

    // Final: +127.5, clip [0,255], /127.5 - 1; store both rows.
    float* dst = out + ((size_t)bc * W_IMG + (size_t)th * 8 + 2 * rr) * W_IMG + (size_t)tw * 8;
    const float inv1275 = 1.0f / 127.5f;
    float o0[8], o1[8];
    #pragma unroll
    for (int c = 0; c < 8; c++) {
        ull x = fadd2(P[c], C127);
        float x0, x1; upk2(x, x0, x1);
        x0 = fminf(fmaxf(x0, 0.0f), 255.0f);
        x1 = fminf(fmaxf(x1, 0.0f), 255.0f);
        o0[c] = fmaf(x0, inv1275, -1.0f);
        o1[c] = fmaf(x1, inv1275, -1.0f);
    }
    *(float4*)(dst)             = make_float4(o0[0], o0[1], o0[2], o0[3]);
    *(float4*)(dst + 4)         = make_float4(o0[4], o0[5], o0[6], o0[7]);
    *(float4*)(dst + W_IMG)     = make_float4(o1[0], o1[1], o1[2], o1[3]);
    *(float4*)(dst + W_IMG + 4) = make_float4(o1[4], o1[5], o1[6], o1[7]);
}

extern "C" void kernel_launch(void* const* d_in, const int* in_sizes, int n_in,
                              void* d_out, int out_size)
{
    // metadata order: input, dct_tensor, dct_scale, idct_tensor, idct_alpha,
    //                 y_table, c_table, factor
    const float* in = (const float*)d_in[0];
    const float* yt = (const float*)d_in[5];
    const float* ct = (const float*)d_in[6];
    const void*  fp = d_in[7];
    float* outp = (float*)d_out;

    dim3 grid(N_TILES / TILES_PER_BLOCK);
    dct_quant_kernel<<<grid, TPB>>>(in, yt, ct, fp, outp);
}

// round 6
// speedup vs baseline: 1.5207x; 1.0414x over previous
#include <cuda_runtime.h>

// B=32, C=3, H=512, W=512 -> tiles: 32*3*64*64 = 393216
#define N_TILES   393216
#define W_IMG     512
#define TPB       256
#define TILES_PER_BLOCK  (TPB / 4)   // 4 threads per tile (packed row-pair each)

typedef unsigned long long ull;

__device__ __forceinline__ ull pk2(float lo, float hi) {
    ull r; asm("mov.b64 %0,{%1,%2};" : "=l"(r) : "f"(lo), "f"(hi)); return r;
}
__device__ __forceinline__ void upk2(ull p, float& lo, float& hi) {
    asm("mov.b64 {%0,%1},%2;" : "=f"(lo), "=f"(hi) : "l"(p));
}
__device__ __forceinline__ ull fadd2(ull a, ull b) {
    ull r; asm("add.rn.f32x2 %0,%1,%2;" : "=l"(r) : "l"(a), "l"(b)); return r;
}
__device__ __forceinline__ ull fsub2(ull a, ull b) {
    ull r; asm("sub.rn.f32x2 %0,%1,%2;" : "=l"(r) : "l"(a), "l"(b)); return r;
}
__device__ __forceinline__ ull fmul2(ull a, ull b) {
    ull r; asm("mul.rn.f32x2 %0,%1,%2;" : "=l"(r) : "l"(a), "l"(b)); return r;
}
__device__ __forceinline__ ull ffma2(ull a, ull b, ull c) {
    ull r; asm("fma.rn.f32x2 %0,%1,%2,%3;" : "=l"(r) : "l"(a), "l"(b), "l"(c)); return r;
}

// Packed constants (row-pair identical).
struct K {
    ull C1, C2, C3, C4, C5, C6, C7;
    ull N1, N2, N5, N7;
};

// Packed 8-point DCT-II (folded 0.5*alpha scaling), butterfly form.
__device__ __forceinline__ void dct8p(ull* t, const K& k) {
    ull s0 = fadd2(t[0], t[7]), s1 = fadd2(t[1], t[6]);
    ull s2 = fadd2(t[2], t[5]), s3 = fadd2(t[3], t[4]);
    ull d0 = fsub2(t[0], t[7]), d1 = fsub2(t[1], t[6]);
    ull d2 = fsub2(t[2], t[5]), d3 = fsub2(t[3], t[4]);
    ull e0 = fadd2(s0, s3), e1 = fadd2(s1, s2);
    ull f0 = fsub2(s0, s3), f1 = fsub2(s1, s2);

    t[0] = fmul2(k.C4, fadd2(e0, e1));
    t[4] = fmul2(k.C4, fsub2(e0, e1));
    t[2] = ffma2(k.C6, f1, fmul2(k.C2, f0));
    t[6] = ffma2(k.N2, f1, fmul2(k.C6, f0));
    t[1] = ffma2(k.C7, d3, ffma2(k.C5, d2, ffma2(k.C3, d1, fmul2(k.C1, d0))));
    t[3] = ffma2(k.N5, d3, ffma2(k.N1, d2, ffma2(k.N7, d1, fmul2(k.C3, d0))));
    t[5] = ffma2(k.C3, d3, ffma2(k.C7, d2, ffma2(k.N1, d1, fmul2(k.C5, d0))));
    t[7] = ffma2(k.N1, d3, ffma2(k.C3, d2, ffma2(k.N5, d1, fmul2(k.C7, d0))));
}

// Packed inverse (transpose matrix; 0.25*idct_alpha folded).
__device__ __forceinline__ void idct8p(ull* t, const K& k) {
    ull a0 = fmul2(k.C4, fadd2(t[0], t[4]));
    ull a1 = fmul2(k.C4, fsub2(t[0], t[4]));
    ull b0 = ffma2(k.C6, t[6], fmul2(k.C2, t[2]));
    ull b1 = ffma2(k.N2, t[6], fmul2(k.C6, t[2]));
    ull E0 = fadd2(a0, b0), E1 = fadd2(a1, b1);
    ull E2 = fsub2(a1, b1), E3 = fsub2(a0, b0);

    ull O0 = ffma2(k.C7, t[7], ffma2(k.C5, t[5], ffma2(k.C3, t[3], fmul2(k.C1, t[1]))));
    ull O1 = ffma2(k.N5, t[7], ffma2(k.N1, t[5], ffma2(k.N7, t[3], fmul2(k.C3, t[1]))));
    ull O2 = ffma2(k.C3, t[7], ffma2(k.C7, t[5], ffma2(k.N1, t[3], fmul2(k.C5, t[1]))));
    ull O3 = ffma2(k.N1, t[7], ffma2(k.C3, t[5], ffma2(k.N5, t[3], fmul2(k.C7, t[1]))));

    t[0] = fadd2(E0, O0);  t[7] = fsub2(E0, O0);
    t[1] = fadd2(E1, O1);  t[6] = fsub2(E1, O1);
    t[2] = fadd2(E2, O2);  t[5] = fsub2(E2, O2);
    t[3] = fadd2(E3, O3);  t[4] = fsub2(E3, O3);
}

// Packed butterfly exchange between P[i] and P[j] across lanes (mask).
#define XSTEPP(I, J, FLAG, MASK) do {                                  \
    ull _s = (FLAG) ? P[I] : P[J];                                     \
    ull _r = __shfl_xor_sync(0xffffffffu, _s, (MASK));                 \
    if (FLAG) P[I] = _r; else P[J] = _r;                               \
} while (0)

// 8x8 transpose on packed row-pairs. Row coord: bit0 = pack-half,
// bit1 = lane bit3, bit2 = lane bit4. Column coord = register index.
__device__ __forceinline__ void xposep(ull P[8], int lane) {
    bool f2 = (lane >> 4) & 1;
    XSTEPP(0, 4, f2, 16);  XSTEPP(1, 5, f2, 16);
    XSTEPP(2, 6, f2, 16);  XSTEPP(3, 7, f2, 16);
    bool f1 = (lane >> 3) & 1;
    XSTEPP(0, 2, f1, 8);   XSTEPP(1, 3, f1, 8);
    XSTEPP(4, 6, f1, 8);   XSTEPP(5, 7, f1, 8);
    // bit0 (pack-half) <-> column bit0: repack halves, register-rename cheap.
    #pragma unroll
    for (int c = 0; c < 8; c += 2) {
        float a0, a1, b0, b1;
        upk2(P[c], a0, a1);
        upk2(P[c + 1], b0, b1);
        P[c]     = pk2(a0, b0);
        P[c + 1] = pk2(a1, b1);
    }
}

__global__ __launch_bounds__(TPB, 6)
void dct_quant_kernel(const float* __restrict__ in,
                      const float* __restrict__ y_table,
                      const float* __restrict__ c_table,
                      const void*  __restrict__ factor_p,
                      float* __restrict__ out)
{
    // Interleaved (q, 1/q) pairs, per channel, flat index u*8+v.
    __shared__ float2 sQ[3][64];

    int tid = threadIdx.x;
    {
        int   iv = *(const int*)factor_p;
        float f  = (iv >= 1 && iv <= (1 << 20)) ? (float)iv : *(const float*)factor_p;
        if (tid < 192) {
            int ch = tid >> 6;
            int j  = tid & 63;
            float q = (ch == 0) ? (y_table[j] * f) : (c_table[j] * (0.5f * f));
            sQ[ch][j] = make_float2(q, 1.0f / q);
        }
    }
    __syncthreads();

    K k;
    k.C1 = pk2( 0.4903926402016152f,  0.4903926402016152f);
    k.C2 = pk2( 0.4619397662556434f,  0.4619397662556434f);
    k.C3 = pk2( 0.4157348061512726f,  0.4157348061512726f);
    k.C4 = pk2( 0.3535533905932738f,  0.3535533905932738f);
    k.C5 = pk2( 0.2777851165098011f,  0.2777851165098011f);
    k.C6 = pk2( 0.1913417161825449f,  0.1913417161825449f);
    k.C7 = pk2( 0.0975451610080641f,  0.0975451610080641f);
    k.N1 = pk2(-0.4903926402016152f, -0.4903926402016152f);
    k.N2 = pk2(-0.4619397662556434f, -0.4619397662556434f);
    k.N5 = pk2(-0.2777851165098011f, -0.2777851165098011f);
    k.N7 = pk2(-0.0975451610080641f, -0.0975451610080641f);
    ull C127 = pk2(127.5f, 127.5f);

    int lane = tid & 31;
    int t  = lane & 7;          // tile within warp
    int rr = (lane >> 3) & 3;   // row-pair index: rows 2rr, 2rr+1

    int tile = (blockIdx.x * (TPB >> 5) + (tid >> 5)) * 8 + t;
    int tw = tile & 63;
    int th = (tile >> 6) & 63;
    int bc = tile >> 12;
    int ch = bc - (bc / 3) * 3;

    const float* src = in + ((size_t)bc * W_IMG + (size_t)th * 8 + 2 * rr) * W_IMG + (size_t)tw * 8;

    ull P[8];

    // Load 2 rows, pack pairs, center: (input+1)*127.5 - 127.5 == input*127.5
    {
        float4 a0 = *(const float4*)(src);
        float4 b0 = *(const float4*)(src + 4);
        float4 a1 = *(const float4*)(src + W_IMG);
        float4 b1 = *(const float4*)(src + W_IMG + 4);
        P[0] = fmul2(pk2(a0.x, a1.x), C127);
        P[1] = fmul2(pk2(a0.y, a1.y), C127);
        P[2] = fmul2(pk2(a0.z, a1.z), C127);
        P[3] = fmul2(pk2(a0.w, a1.w), C127);
        P[4] = fmul2(pk2(b0.x, b1.x), C127);
        P[5] = fmul2(pk2(b0.y, b1.y), C127);
        P[6] = fmul2(pk2(b0.z, b1.z), C127);
        P[7] = fmul2(pk2(b0.w, b1.w), C127);
    }

    // Forward: DCT over regs, transpose, DCT over regs
    dct8p(P, k);
    xposep(P, lane);            // lane/pack coord = v, regs = x
    dct8p(P, k);                // regs = u; element F[u][v], v = 2rr + half

    // Quantize / dequantize (diff_round: r + (x-r)^3). q index = u*8 + v.
    {
        const float4* qp = (const float4*)&sQ[ch][0] + rr;   // (q0,qi0,q1,qi1)
        #pragma unroll
        for (int c = 0; c < 8; c++) {
            float4 qq = qp[c * 4];
            ull QI = pk2(qq.y, qq.w);
            ull QV = pk2(qq.x, qq.z);
            ull q  = fmul2(P[c], QI);
            float q0, q1; upk2(q, q0, q1);
            ull rp = pk2(rintf(q0), rintf(q1));
            ull e  = fsub2(q, rp);
            ull dr = ffma2(fmul2(e, e), e, rp);
            P[c] = fmul2(dr, QV);
        }
    }

    // Inverse: IDCT over regs, transpose, IDCT over regs
    idct8p(P, k);               // regs = x spatial
    xposep(P, lane);            // lane/pack coord = x, regs = v
    idct8p(P, k);               // regs/pack = spatial rows

    // Final: +127.5, clip [0,255], /127.5 - 1; scalar clamp, packed scale.
    float* dst = out + ((size_t)bc * W_IMG + (size_t)th * 8 + 2 * rr) * W_IMG + (size_t)tw * 8;
    ull INV   = pk2(1.0f / 127.5f, 1.0f / 127.5f);
    ull MONE  = pk2(-1.0f, -1.0f);
    float o0[8], o1[8];
    #pragma unroll
    for (int c = 0; c < 8; c++) {
        ull x = fadd2(P[c], C127);
        float x0, x1; upk2(x, x0, x1);
        x0 = fminf(fmaxf(x0, 0.0f), 255.0f);
        x1 = fminf(fmaxf(x1, 0.0f), 255.0f);
        ull y = ffma2(pk2(x0, x1), INV, MONE);
        upk2(y, o0[c], o1[c]);
    }
    *(float4*)(dst)             = make_float4(o0[0], o0[1], o0[2], o0[3]);
    *(float4*)(dst + 4)         = make_float4(o0[4], o0[5], o0[6], o0[7]);
    *(float4*)(dst + W_IMG)     = make_float4(o1[0], o1[1], o1[2], o1[3]);
    *(float4*)(dst + W_IMG + 4) = make_float4(o1[4], o1[5], o1[6], o1[7]);
}

extern "C" void kernel_launch(void* const* d_in, const int* in_sizes, int n_in,
                              void* d_out, int out_size)
{
    // metadata order: input, dct_tensor, dct_scale, idct_tensor, idct_alpha,
    //                 y_table, c_table, factor
    const float* in = (const float*)d_in[0];
    const float* yt = (const float*)d_in[5];
    const float* ct = (const float*)d_in[6];
    const void*  fp = d_in[7];
    float* outp = (float*)d_out;

    dim3 grid(N_TILES / TILES_PER_BLOCK);
    dct_quant_kernel<<<grid, TPB>>>(in, yt, ct, fp, outp);
}